// round 12
// baseline (speedup 1.0000x reference)
#include <cuda_runtime.h>
#include <cuda_bf16.h>
#include <math.h>

#define NUM_HEADS 32
#define HEAD_DIM  128
#define HIDDEN    4096
#define QLEN      1024
#define KVLEN     4096

// ---------------------------------------------------------------------------
// Scratch (device globals — no allocations allowed in kernel_launch)
// ---------------------------------------------------------------------------
__device__ float g_q[(size_t)QLEN * HIDDEN];                      // 16 MB
__device__ float g_k[(size_t)KVLEN * HIDDEN];                     // 64 MB
__device__ float g_v[(size_t)KVLEN * HIDDEN];                     // 64 MB
__device__ float g_s[(size_t)NUM_HEADS * QLEN * KVLEN];           // 512 MB
__device__ float g_attn[(size_t)QLEN * HIDDEN];                   // 16 MB

// ---------------------------------------------------------------------------
// NT SGEMM: C[M,N] = alpha * A[M,K] * B[N,K]^T
// A row-major (lda), B row-major (ldb) — both K-contiguous.
// M = gridDim.y*128, N = gridDim.x*128 (all dims multiples of 128 here).
// Batched via blockIdx.z with element strides sA/sB/sC.
// ---------------------------------------------------------------------------
#define BM 128
#define BN 128
#define BK 8
#define TM 8
#define TN 8

__global__ __launch_bounds__(256, 2)
void gemm_nt(const float* __restrict__ A, const float* __restrict__ B,
             float* __restrict__ C,
             int K, int lda, int ldb, int ldc,
             long sA, long sB, long sC, float alpha)
{
    A += (long)blockIdx.z * sA;
    B += (long)blockIdx.z * sB;
    C += (long)blockIdx.z * sC;
    const int bm = blockIdx.y * BM;
    const int bn = blockIdx.x * BN;

    __shared__ float As[BK][BM];
    __shared__ float Bs[BK][BN];

    const int tid = threadIdx.x;          // 0..255
    const int lr  = tid >> 1;             // 0..127 (tile row for loads)
    const int lc  = (tid & 1) * 4;        // 0 or 4 (k-col for loads)
    const int ty  = tid >> 4;             // 0..15
    const int tx  = tid & 15;             // 0..15

    const float* Aptr = A + (long)(bm + lr) * lda + lc;
    const float* Bptr = B + (long)(bn + lr) * ldb + lc;

    float acc[TM][TN];
#pragma unroll
    for (int i = 0; i < TM; i++)
#pragma unroll
        for (int j = 0; j < TN; j++) acc[i][j] = 0.f;

    for (int k0 = 0; k0 < K; k0 += BK) {
        float4 a4 = *(const float4*)(Aptr + k0);
        float4 b4 = *(const float4*)(Bptr + k0);
        __syncthreads();
        As[lc + 0][lr] = a4.x; As[lc + 1][lr] = a4.y;
        As[lc + 2][lr] = a4.z; As[lc + 3][lr] = a4.w;
        Bs[lc + 0][lr] = b4.x; Bs[lc + 1][lr] = b4.y;
        Bs[lc + 2][lr] = b4.z; Bs[lc + 3][lr] = b4.w;
        __syncthreads();

#pragma unroll
        for (int kk = 0; kk < BK; kk++) {
            float4 a0 = *(const float4*)&As[kk][ty * TM];
            float4 a1 = *(const float4*)&As[kk][ty * TM + 4];
            float4 b0 = *(const float4*)&Bs[kk][tx * TN];
            float4 b1 = *(const float4*)&Bs[kk][tx * TN + 4];
            float ar[TM] = {a0.x, a0.y, a0.z, a0.w, a1.x, a1.y, a1.z, a1.w};
            float br[TN] = {b0.x, b0.y, b0.z, b0.w, b1.x, b1.y, b1.z, b1.w};
#pragma unroll
            for (int i = 0; i < TM; i++)
#pragma unroll
                for (int j = 0; j < TN; j++) acc[i][j] += ar[i] * br[j];
        }
    }

#pragma unroll
    for (int i = 0; i < TM; i++) {
        float* crow = C + (long)(bm + ty * TM + i) * ldc + bn + tx * TN;
#pragma unroll
        for (int j = 0; j < TN; j++) crow[j] = alpha * acc[i][j];
    }
}

// ---------------------------------------------------------------------------
// NN SGEMM: C[M,N] = alpha * A[M,K] * B[K,N]
// A row-major (lda, K-contiguous), B row-major (ldb, N-contiguous).
// ---------------------------------------------------------------------------
__global__ __launch_bounds__(256, 2)
void gemm_nn(const float* __restrict__ A, const float* __restrict__ B,
             float* __restrict__ C,
             int K, int lda, int ldb, int ldc,
             long sA, long sB, long sC, float alpha)
{
    A += (long)blockIdx.z * sA;
    B += (long)blockIdx.z * sB;
    C += (long)blockIdx.z * sC;
    const int bm = blockIdx.y * BM;
    const int bn = blockIdx.x * BN;

    __shared__ float As[BK][BM];
    __shared__ float Bs[BK][BN];

    const int tid = threadIdx.x;
    const int lr  = tid >> 1;             // A tile row
    const int lc  = (tid & 1) * 4;        // A tile k-col
    const int br_ = tid >> 5;             // B tile k-row (0..7)
    const int bc  = (tid & 31) * 4;       // B tile n-col
    const int ty  = tid >> 4;
    const int tx  = tid & 15;

    const float* Aptr = A + (long)(bm + lr) * lda + lc;
    const float* Bptr = B + bn + bc;

    float acc[TM][TN];
#pragma unroll
    for (int i = 0; i < TM; i++)
#pragma unroll
        for (int j = 0; j < TN; j++) acc[i][j] = 0.f;

    for (int k0 = 0; k0 < K; k0 += BK) {
        float4 a4 = *(const float4*)(Aptr + k0);
        float4 b4 = *(const float4*)(Bptr + (long)(k0 + br_) * ldb);
        __syncthreads();
        As[lc + 0][lr] = a4.x; As[lc + 1][lr] = a4.y;
        As[lc + 2][lr] = a4.z; As[lc + 3][lr] = a4.w;
        *(float4*)&Bs[br_][bc] = b4;
        __syncthreads();

#pragma unroll
        for (int kk = 0; kk < BK; kk++) {
            float4 a0 = *(const float4*)&As[kk][ty * TM];
            float4 a1 = *(const float4*)&As[kk][ty * TM + 4];
            float4 b0 = *(const float4*)&Bs[kk][tx * TN];
            float4 b1 = *(const float4*)&Bs[kk][tx * TN + 4];
            float ar[TM] = {a0.x, a0.y, a0.z, a0.w, a1.x, a1.y, a1.z, a1.w};
            float br[TN] = {b0.x, b0.y, b0.z, b0.w, b1.x, b1.y, b1.z, b1.w};
#pragma unroll
            for (int i = 0; i < TM; i++)
#pragma unroll
                for (int j = 0; j < TN; j++) acc[i][j] += ar[i] * br[j];
        }
    }

#pragma unroll
    for (int i = 0; i < TM; i++) {
        float* crow = C + (long)(bm + ty * TM + i) * ldc + bn + tx * TN;
#pragma unroll
        for (int j = 0; j < TN; j++) crow[j] = alpha * acc[i][j];
    }
}

// ---------------------------------------------------------------------------
// Per-head RMSNorm over contiguous 128-element segments (in-place).
// blockIdx.x = segment index; 128 threads, one element each.
// ---------------------------------------------------------------------------
__global__ void rmsnorm_128(float* __restrict__ x, const float* __restrict__ w)
{
    float* p = x + (long)blockIdx.x * HEAD_DIM;
    const int tid  = threadIdx.x;
    const int lane = tid & 31;
    const int wid  = tid >> 5;

    float v  = p[tid];
    float ss = v * v;
#pragma unroll
    for (int o = 16; o; o >>= 1) ss += __shfl_xor_sync(0xffffffffu, ss, o);

    __shared__ float red[4];
    if (lane == 0) red[wid] = ss;
    __syncthreads();
    float tot = red[0] + red[1] + red[2] + red[3];
    float r = rsqrtf(tot * (1.0f / HEAD_DIM) + 1e-5f);
    p[tid] = w[tid] * v * r;
}

// ---------------------------------------------------------------------------
// Row softmax over KVLEN columns, in place. blockIdx.x = row; 256 threads.
// ---------------------------------------------------------------------------
__global__ void softmax_rows(float* __restrict__ S)
{
    float* row = S + (size_t)blockIdx.x * KVLEN;
    const int tid  = threadIdx.x;
    const int lane = tid & 31;
    const int wid  = tid >> 5;
    __shared__ float red[8];

    float m = -1e30f;
    for (int i = tid; i < KVLEN; i += 256) m = fmaxf(m, row[i]);
#pragma unroll
    for (int o = 16; o; o >>= 1) m = fmaxf(m, __shfl_xor_sync(0xffffffffu, m, o));
    if (lane == 0) red[wid] = m;
    __syncthreads();
    m = red[0];
#pragma unroll
    for (int w2 = 1; w2 < 8; w2++) m = fmaxf(m, red[w2]);

    float sum = 0.f;
    for (int i = tid; i < KVLEN; i += 256) {
        float e = __expf(row[i] - m);
        row[i] = e;
        sum += e;
    }
#pragma unroll
    for (int o = 16; o; o >>= 1) sum += __shfl_xor_sync(0xffffffffu, sum, o);
    __syncthreads();
    if (lane == 0) red[wid] = sum;
    __syncthreads();
    sum = 0.f;
#pragma unroll
    for (int w2 = 0; w2 < 8; w2++) sum += red[w2];
    float inv = 1.0f / sum;
    for (int i = tid; i < KVLEN; i += 256) row[i] *= inv;
}

// ---------------------------------------------------------------------------
// Launch
// ---------------------------------------------------------------------------
extern "C" void kernel_launch(void* const* d_in, const int* in_sizes, int n_in,
                              void* d_out, int out_size)
{
    const float* hs = (const float*)d_in[0];   // [1, 1024, 4096]
    const float* kv = (const float*)d_in[1];   // [1, 4096, 4096]
    const float* wq = (const float*)d_in[2];   // [4096, 4096]
    const float* wk = (const float*)d_in[3];
    const float* wv = (const float*)d_in[4];
    const float* wo = (const float*)d_in[5];
    const float* qw = (const float*)d_in[6];   // [128]
    const float* kw = (const float*)d_in[7];   // [128]
    float* out = (float*)d_out;                // [1, 1024, 4096]

    float *q, *k, *v, *s, *attn;
    cudaGetSymbolAddress((void**)&q,    g_q);
    cudaGetSymbolAddress((void**)&k,    g_k);
    cudaGetSymbolAddress((void**)&v,    g_v);
    cudaGetSymbolAddress((void**)&s,    g_s);
    cudaGetSymbolAddress((void**)&attn, g_attn);

    const dim3 thr(256);
    const float inv_sqrt_d = 0.08838834764831845f;   // 1/sqrt(128)

    // Q = hs @ wq^T   [1024, 4096]
    gemm_nt<<<dim3(HIDDEN / BN, QLEN / BM, 1), thr>>>(
        hs, wq, q, HIDDEN, HIDDEN, HIDDEN, HIDDEN, 0, 0, 0, 1.0f);
    // K = kv @ wk^T   [4096, 4096]
    gemm_nt<<<dim3(HIDDEN / BN, KVLEN / BM, 1), thr>>>(
        kv, wk, k, HIDDEN, HIDDEN, HIDDEN, HIDDEN, 0, 0, 0, 1.0f);
    // V = kv @ wv^T   [4096, 4096]
    gemm_nt<<<dim3(HIDDEN / BN, KVLEN / BM, 1), thr>>>(
        kv, wv, v, HIDDEN, HIDDEN, HIDDEN, HIDDEN, 0, 0, 0, 1.0f);

    // per-head RMSNorm (each row of Q/K is 32 heads x 128 contiguous dims)
    rmsnorm_128<<<QLEN * NUM_HEADS, HEAD_DIM>>>(q, qw);
    rmsnorm_128<<<KVLEN * NUM_HEADS, HEAD_DIM>>>(k, kw);

    // scores[h] = (Q_h @ K_h^T) / sqrt(d)  -> [32][1024][4096]
    gemm_nt<<<dim3(KVLEN / BN, QLEN / BM, NUM_HEADS), thr>>>(
        q, k, s, HEAD_DIM, HIDDEN, HIDDEN, KVLEN,
        (long)HEAD_DIM, (long)HEAD_DIM, (long)QLEN * KVLEN, inv_sqrt_d);

    // softmax over keys
    softmax_rows<<<NUM_HEADS * QLEN, 256>>>(s);

    // attn[h] = probs[h] @ V_h   -> columns h*128..h*128+127 of [1024, 4096]
    gemm_nn<<<dim3(HEAD_DIM / BN == 0 ? 1 : HEAD_DIM / BN, QLEN / BM, NUM_HEADS), thr>>>(
        s, v, attn, KVLEN, KVLEN, HIDDEN, HIDDEN,
        (long)QLEN * KVLEN, (long)HEAD_DIM, (long)HEAD_DIM, 1.0f);

    // out = attn @ wo^T   [1024, 4096]
    gemm_nt<<<dim3(HIDDEN / BN, QLEN / BM, 1), thr>>>(
        attn, wo, out, HIDDEN, HIDDEN, HIDDEN, HIDDEN, 0, 0, 0, 1.0f);
}

// round 13
// speedup vs baseline: 1.0002x; 1.0002x over previous
#include <cuda_runtime.h>
#include <cuda_bf16.h>
#include <math.h>

#define NUM_HEADS 32
#define HEAD_DIM  128
#define HIDDEN    4096
#define QLEN      1024
#define KVLEN     4096

// ---------------------------------------------------------------------------
// Scratch (device globals — no allocations allowed in kernel_launch)
// ---------------------------------------------------------------------------
__device__ float g_q[(size_t)QLEN * HIDDEN];                      // 16 MB
__device__ float g_k[(size_t)KVLEN * HIDDEN];                     // 64 MB
__device__ float g_v[(size_t)KVLEN * HIDDEN];                     // 64 MB
__device__ float g_s[(size_t)NUM_HEADS * QLEN * KVLEN];           // 512 MB
__device__ float g_attn[(size_t)QLEN * HIDDEN];                   // 16 MB

// ---------------------------------------------------------------------------
// NT SGEMM: C[M,N] = alpha * A[M,K] * B[N,K]^T
// A row-major (lda), B row-major (ldb) — both K-contiguous.
// M = gridDim.y*128, N = gridDim.x*128 (all dims multiples of 128 here).
// Batched via blockIdx.z with element strides sA/sB/sC.
// ---------------------------------------------------------------------------
#define BM 128
#define BN 128
#define BK 8
#define TM 8
#define TN 8

__global__ __launch_bounds__(256, 2)
void gemm_nt(const float* __restrict__ A, const float* __restrict__ B,
             float* __restrict__ C,
             int K, int lda, int ldb, int ldc,
             long sA, long sB, long sC, float alpha)
{
    A += (long)blockIdx.z * sA;
    B += (long)blockIdx.z * sB;
    C += (long)blockIdx.z * sC;
    const int bm = blockIdx.y * BM;
    const int bn = blockIdx.x * BN;

    __shared__ float As[BK][BM];
    __shared__ float Bs[BK][BN];

    const int tid = threadIdx.x;          // 0..255
    const int lr  = tid >> 1;             // 0..127 (tile row for loads)
    const int lc  = (tid & 1) * 4;        // 0 or 4 (k-col for loads)
    const int ty  = tid >> 4;             // 0..15
    const int tx  = tid & 15;             // 0..15

    const float* Aptr = A + (long)(bm + lr) * lda + lc;
    const float* Bptr = B + (long)(bn + lr) * ldb + lc;

    float acc[TM][TN];
#pragma unroll
    for (int i = 0; i < TM; i++)
#pragma unroll
        for (int j = 0; j < TN; j++) acc[i][j] = 0.f;

    for (int k0 = 0; k0 < K; k0 += BK) {
        float4 a4 = *(const float4*)(Aptr + k0);
        float4 b4 = *(const float4*)(Bptr + k0);
        __syncthreads();
        As[lc + 0][lr] = a4.x; As[lc + 1][lr] = a4.y;
        As[lc + 2][lr] = a4.z; As[lc + 3][lr] = a4.w;
        Bs[lc + 0][lr] = b4.x; Bs[lc + 1][lr] = b4.y;
        Bs[lc + 2][lr] = b4.z; Bs[lc + 3][lr] = b4.w;
        __syncthreads();

#pragma unroll
        for (int kk = 0; kk < BK; kk++) {
            float4 a0 = *(const float4*)&As[kk][ty * TM];
            float4 a1 = *(const float4*)&As[kk][ty * TM + 4];
            float4 b0 = *(const float4*)&Bs[kk][tx * TN];
            float4 b1 = *(const float4*)&Bs[kk][tx * TN + 4];
            float ar[TM] = {a0.x, a0.y, a0.z, a0.w, a1.x, a1.y, a1.z, a1.w};
            float br[TN] = {b0.x, b0.y, b0.z, b0.w, b1.x, b1.y, b1.z, b1.w};
#pragma unroll
            for (int i = 0; i < TM; i++)
#pragma unroll
                for (int j = 0; j < TN; j++) acc[i][j] += ar[i] * br[j];
        }
    }

#pragma unroll
    for (int i = 0; i < TM; i++) {
        float* crow = C + (long)(bm + ty * TM + i) * ldc + bn + tx * TN;
#pragma unroll
        for (int j = 0; j < TN; j++) crow[j] = alpha * acc[i][j];
    }
}

// ---------------------------------------------------------------------------
// NN SGEMM: C[M,N] = alpha * A[M,K] * B[K,N]
// A row-major (lda, K-contiguous), B row-major (ldb, N-contiguous).
// ---------------------------------------------------------------------------
__global__ __launch_bounds__(256, 2)
void gemm_nn(const float* __restrict__ A, const float* __restrict__ B,
             float* __restrict__ C,
             int K, int lda, int ldb, int ldc,
             long sA, long sB, long sC, float alpha)
{
    A += (long)blockIdx.z * sA;
    B += (long)blockIdx.z * sB;
    C += (long)blockIdx.z * sC;
    const int bm = blockIdx.y * BM;
    const int bn = blockIdx.x * BN;

    __shared__ float As[BK][BM];
    __shared__ float Bs[BK][BN];

    const int tid = threadIdx.x;
    const int lr  = tid >> 1;             // A tile row
    const int lc  = (tid & 1) * 4;        // A tile k-col
    const int br_ = tid >> 5;             // B tile k-row (0..7)
    const int bc  = (tid & 31) * 4;       // B tile n-col
    const int ty  = tid >> 4;
    const int tx  = tid & 15;

    const float* Aptr = A + (long)(bm + lr) * lda + lc;
    const float* Bptr = B + bn + bc;

    float acc[TM][TN];
#pragma unroll
    for (int i = 0; i < TM; i++)
#pragma unroll
        for (int j = 0; j < TN; j++) acc[i][j] = 0.f;

    for (int k0 = 0; k0 < K; k0 += BK) {
        float4 a4 = *(const float4*)(Aptr + k0);
        float4 b4 = *(const float4*)(Bptr + (long)(k0 + br_) * ldb);
        __syncthreads();
        As[lc + 0][lr] = a4.x; As[lc + 1][lr] = a4.y;
        As[lc + 2][lr] = a4.z; As[lc + 3][lr] = a4.w;
        *(float4*)&Bs[br_][bc] = b4;
        __syncthreads();

#pragma unroll
        for (int kk = 0; kk < BK; kk++) {
            float4 a0 = *(const float4*)&As[kk][ty * TM];
            float4 a1 = *(const float4*)&As[kk][ty * TM + 4];
            float4 b0 = *(const float4*)&Bs[kk][tx * TN];
            float4 b1 = *(const float4*)&Bs[kk][tx * TN + 4];
            float ar[TM] = {a0.x, a0.y, a0.z, a0.w, a1.x, a1.y, a1.z, a1.w};
            float br[TN] = {b0.x, b0.y, b0.z, b0.w, b1.x, b1.y, b1.z, b1.w};
#pragma unroll
            for (int i = 0; i < TM; i++)
#pragma unroll
                for (int j = 0; j < TN; j++) acc[i][j] += ar[i] * br[j];
        }
    }

#pragma unroll
    for (int i = 0; i < TM; i++) {
        float* crow = C + (long)(bm + ty * TM + i) * ldc + bn + tx * TN;
#pragma unroll
        for (int j = 0; j < TN; j++) crow[j] = alpha * acc[i][j];
    }
}

// ---------------------------------------------------------------------------
// Per-head RMSNorm over contiguous 128-element segments (in-place).
// blockIdx.x = segment index; 128 threads, one element each.
// ---------------------------------------------------------------------------
__global__ void rmsnorm_128(float* __restrict__ x, const float* __restrict__ w)
{
    float* p = x + (long)blockIdx.x * HEAD_DIM;
    const int tid  = threadIdx.x;
    const int lane = tid & 31;
    const int wid  = tid >> 5;

    float v  = p[tid];
    float ss = v * v;
#pragma unroll
    for (int o = 16; o; o >>= 1) ss += __shfl_xor_sync(0xffffffffu, ss, o);

    __shared__ float red[4];
    if (lane == 0) red[wid] = ss;
    __syncthreads();
    float tot = red[0] + red[1] + red[2] + red[3];
    float r = rsqrtf(tot * (1.0f / HEAD_DIM) + 1e-5f);
    p[tid] = w[tid] * v * r;
}

// ---------------------------------------------------------------------------
// Row softmax over KVLEN columns, in place. blockIdx.x = row; 256 threads.
// ---------------------------------------------------------------------------
__global__ void softmax_rows(float* __restrict__ S)
{
    float* row = S + (size_t)blockIdx.x * KVLEN;
    const int tid  = threadIdx.x;
    const int lane = tid & 31;
    const int wid  = tid >> 5;
    __shared__ float red[8];

    float m = -1e30f;
    for (int i = tid; i < KVLEN; i += 256) m = fmaxf(m, row[i]);
#pragma unroll
    for (int o = 16; o; o >>= 1) m = fmaxf(m, __shfl_xor_sync(0xffffffffu, m, o));
    if (lane == 0) red[wid] = m;
    __syncthreads();
    m = red[0];
#pragma unroll
    for (int w2 = 1; w2 < 8; w2++) m = fmaxf(m, red[w2]);

    float sum = 0.f;
    for (int i = tid; i < KVLEN; i += 256) {
        float e = __expf(row[i] - m);
        row[i] = e;
        sum += e;
    }
#pragma unroll
    for (int o = 16; o; o >>= 1) sum += __shfl_xor_sync(0xffffffffu, sum, o);
    __syncthreads();
    if (lane == 0) red[wid] = sum;
    __syncthreads();
    sum = 0.f;
#pragma unroll
    for (int w2 = 0; w2 < 8; w2++) sum += red[w2];
    float inv = 1.0f / sum;
    for (int i = tid; i < KVLEN; i += 256) row[i] *= inv;
}

// ---------------------------------------------------------------------------
// Launch
// ---------------------------------------------------------------------------
extern "C" void kernel_launch(void* const* d_in, const int* in_sizes, int n_in,
                              void* d_out, int out_size)
{
    const float* hs = (const float*)d_in[0];   // [1, 1024, 4096]
    const float* kv = (const float*)d_in[1];   // [1, 4096, 4096]
    const float* wq = (const float*)d_in[2];   // [4096, 4096]
    const float* wk = (const float*)d_in[3];
    const float* wv = (const float*)d_in[4];
    const float* wo = (const float*)d_in[5];
    const float* qw = (const float*)d_in[6];   // [128]
    const float* kw = (const float*)d_in[7];   // [128]
    float* out = (float*)d_out;                // [1, 1024, 4096]

    float *q, *k, *v, *s, *attn;
    cudaGetSymbolAddress((void**)&q,    g_q);
    cudaGetSymbolAddress((void**)&k,    g_k);
    cudaGetSymbolAddress((void**)&v,    g_v);
    cudaGetSymbolAddress((void**)&s,    g_s);
    cudaGetSymbolAddress((void**)&attn, g_attn);

    const dim3 thr(256);
    const float inv_sqrt_d = 0.08838834764831845f;   // 1/sqrt(128)

    // Q = hs @ wq^T   [1024, 4096]
    gemm_nt<<<dim3(HIDDEN / BN, QLEN / BM, 1), thr>>>(
        hs, wq, q, HIDDEN, HIDDEN, HIDDEN, HIDDEN, 0, 0, 0, 1.0f);
    // K = kv @ wk^T   [4096, 4096]
    gemm_nt<<<dim3(HIDDEN / BN, KVLEN / BM, 1), thr>>>(
        kv, wk, k, HIDDEN, HIDDEN, HIDDEN, HIDDEN, 0, 0, 0, 1.0f);
    // V = kv @ wv^T   [4096, 4096]
    gemm_nt<<<dim3(HIDDEN / BN, KVLEN / BM, 1), thr>>>(
        kv, wv, v, HIDDEN, HIDDEN, HIDDEN, HIDDEN, 0, 0, 0, 1.0f);

    // per-head RMSNorm (each row of Q/K is 32 heads x 128 contiguous dims)
    rmsnorm_128<<<QLEN * NUM_HEADS, HEAD_DIM>>>(q, qw);
    rmsnorm_128<<<KVLEN * NUM_HEADS, HEAD_DIM>>>(k, kw);

    // scores[h] = (Q_h @ K_h^T) / sqrt(d)  -> [32][1024][4096]
    gemm_nt<<<dim3(KVLEN / BN, QLEN / BM, NUM_HEADS), thr>>>(
        q, k, s, HEAD_DIM, HIDDEN, HIDDEN, KVLEN,
        (long)HEAD_DIM, (long)HEAD_DIM, (long)QLEN * KVLEN, inv_sqrt_d);

    // softmax over keys
    softmax_rows<<<NUM_HEADS * QLEN, 256>>>(s);

    // attn[h] = probs[h] @ V_h   -> columns h*128..h*128+127 of [1024, 4096]
    gemm_nn<<<dim3(HEAD_DIM / BN == 0 ? 1 : HEAD_DIM / BN, QLEN / BM, NUM_HEADS), thr>>>(
        s, v, attn, KVLEN, KVLEN, HIDDEN, HIDDEN,
        (long)QLEN * KVLEN, (long)HEAD_DIM, (long)HEAD_DIM, 1.0f);

    // out = attn @ wo^T   [1024, 4096]
    gemm_nt<<<dim3(HIDDEN / BN, QLEN / BM, 1), thr>>>(
        attn, wo, out, HIDDEN, HIDDEN, HIDDEN, HIDDEN, 0, 0, 0, 1.0f);
}

// round 14
// speedup vs baseline: 1.0019x; 1.0017x over previous
#include <cuda_runtime.h>
#include <cuda_bf16.h>
#include <math.h>

#define NUM_HEADS 32
#define HEAD_DIM  128
#define HIDDEN    4096
#define QLEN      1024
#define KVLEN     4096

// ---------------------------------------------------------------------------
// Scratch (device globals — no allocations allowed in kernel_launch)
// ---------------------------------------------------------------------------
__device__ float g_q[(size_t)QLEN * HIDDEN];                      // 16 MB
__device__ float g_k[(size_t)KVLEN * HIDDEN];                     // 64 MB
__device__ float g_v[(size_t)KVLEN * HIDDEN];                     // 64 MB
__device__ float g_s[(size_t)NUM_HEADS * QLEN * KVLEN];           // 512 MB
__device__ float g_attn[(size_t)QLEN * HIDDEN];                   // 16 MB

// ---------------------------------------------------------------------------
// NT SGEMM: C[M,N] = alpha * A[M,K] * B[N,K]^T
// A row-major (lda), B row-major (ldb) — both K-contiguous.
// M = gridDim.y*128, N = gridDim.x*128 (all dims multiples of 128 here).
// Batched via blockIdx.z with element strides sA/sB/sC.
// ---------------------------------------------------------------------------
#define BM 128
#define BN 128
#define BK 8
#define TM 8
#define TN 8

__global__ __launch_bounds__(256, 2)
void gemm_nt(const float* __restrict__ A, const float* __restrict__ B,
             float* __restrict__ C,
             int K, int lda, int ldb, int ldc,
             long sA, long sB, long sC, float alpha)
{
    A += (long)blockIdx.z * sA;
    B += (long)blockIdx.z * sB;
    C += (long)blockIdx.z * sC;
    const int bm = blockIdx.y * BM;
    const int bn = blockIdx.x * BN;

    __shared__ float As[BK][BM];
    __shared__ float Bs[BK][BN];

    const int tid = threadIdx.x;          // 0..255
    const int lr  = tid >> 1;             // 0..127 (tile row for loads)
    const int lc  = (tid & 1) * 4;        // 0 or 4 (k-col for loads)
    const int ty  = tid >> 4;             // 0..15
    const int tx  = tid & 15;             // 0..15

    const float* Aptr = A + (long)(bm + lr) * lda + lc;
    const float* Bptr = B + (long)(bn + lr) * ldb + lc;

    float acc[TM][TN];
#pragma unroll
    for (int i = 0; i < TM; i++)
#pragma unroll
        for (int j = 0; j < TN; j++) acc[i][j] = 0.f;

    for (int k0 = 0; k0 < K; k0 += BK) {
        float4 a4 = *(const float4*)(Aptr + k0);
        float4 b4 = *(const float4*)(Bptr + k0);
        __syncthreads();
        As[lc + 0][lr] = a4.x; As[lc + 1][lr] = a4.y;
        As[lc + 2][lr] = a4.z; As[lc + 3][lr] = a4.w;
        Bs[lc + 0][lr] = b4.x; Bs[lc + 1][lr] = b4.y;
        Bs[lc + 2][lr] = b4.z; Bs[lc + 3][lr] = b4.w;
        __syncthreads();

#pragma unroll
        for (int kk = 0; kk < BK; kk++) {
            float4 a0 = *(const float4*)&As[kk][ty * TM];
            float4 a1 = *(const float4*)&As[kk][ty * TM + 4];
            float4 b0 = *(const float4*)&Bs[kk][tx * TN];
            float4 b1 = *(const float4*)&Bs[kk][tx * TN + 4];
            float ar[TM] = {a0.x, a0.y, a0.z, a0.w, a1.x, a1.y, a1.z, a1.w};
            float br[TN] = {b0.x, b0.y, b0.z, b0.w, b1.x, b1.y, b1.z, b1.w};
#pragma unroll
            for (int i = 0; i < TM; i++)
#pragma unroll
                for (int j = 0; j < TN; j++) acc[i][j] += ar[i] * br[j];
        }
    }

#pragma unroll
    for (int i = 0; i < TM; i++) {
        float* crow = C + (long)(bm + ty * TM + i) * ldc + bn + tx * TN;
#pragma unroll
        for (int j = 0; j < TN; j++) crow[j] = alpha * acc[i][j];
    }
}

// ---------------------------------------------------------------------------
// NN SGEMM: C[M,N] = alpha * A[M,K] * B[K,N]
// A row-major (lda, K-contiguous), B row-major (ldb, N-contiguous).
// ---------------------------------------------------------------------------
__global__ __launch_bounds__(256, 2)
void gemm_nn(const float* __restrict__ A, const float* __restrict__ B,
             float* __restrict__ C,
             int K, int lda, int ldb, int ldc,
             long sA, long sB, long sC, float alpha)
{
    A += (long)blockIdx.z * sA;
    B += (long)blockIdx.z * sB;
    C += (long)blockIdx.z * sC;
    const int bm = blockIdx.y * BM;
    const int bn = blockIdx.x * BN;

    __shared__ float As[BK][BM];
    __shared__ float Bs[BK][BN];

    const int tid = threadIdx.x;
    const int lr  = tid >> 1;             // A tile row
    const int lc  = (tid & 1) * 4;        // A tile k-col
    const int br_ = tid >> 5;             // B tile k-row (0..7)
    const int bc  = (tid & 31) * 4;       // B tile n-col
    const int ty  = tid >> 4;
    const int tx  = tid & 15;

    const float* Aptr = A + (long)(bm + lr) * lda + lc;
    const float* Bptr = B + bn + bc;

    float acc[TM][TN];
#pragma unroll
    for (int i = 0; i < TM; i++)
#pragma unroll
        for (int j = 0; j < TN; j++) acc[i][j] = 0.f;

    for (int k0 = 0; k0 < K; k0 += BK) {
        float4 a4 = *(const float4*)(Aptr + k0);
        float4 b4 = *(const float4*)(Bptr + (long)(k0 + br_) * ldb);
        __syncthreads();
        As[lc + 0][lr] = a4.x; As[lc + 1][lr] = a4.y;
        As[lc + 2][lr] = a4.z; As[lc + 3][lr] = a4.w;
        *(float4*)&Bs[br_][bc] = b4;
        __syncthreads();

#pragma unroll
        for (int kk = 0; kk < BK; kk++) {
            float4 a0 = *(const float4*)&As[kk][ty * TM];
            float4 a1 = *(const float4*)&As[kk][ty * TM + 4];
            float4 b0 = *(const float4*)&Bs[kk][tx * TN];
            float4 b1 = *(const float4*)&Bs[kk][tx * TN + 4];
            float ar[TM] = {a0.x, a0.y, a0.z, a0.w, a1.x, a1.y, a1.z, a1.w};
            float br[TN] = {b0.x, b0.y, b0.z, b0.w, b1.x, b1.y, b1.z, b1.w};
#pragma unroll
            for (int i = 0; i < TM; i++)
#pragma unroll
                for (int j = 0; j < TN; j++) acc[i][j] += ar[i] * br[j];
        }
    }

#pragma unroll
    for (int i = 0; i < TM; i++) {
        float* crow = C + (long)(bm + ty * TM + i) * ldc + bn + tx * TN;
#pragma unroll
        for (int j = 0; j < TN; j++) crow[j] = alpha * acc[i][j];
    }
}

// ---------------------------------------------------------------------------
// Per-head RMSNorm over contiguous 128-element segments (in-place).
// blockIdx.x = segment index; 128 threads, one element each.
// ---------------------------------------------------------------------------
__global__ void rmsnorm_128(float* __restrict__ x, const float* __restrict__ w)
{
    float* p = x + (long)blockIdx.x * HEAD_DIM;
    const int tid  = threadIdx.x;
    const int lane = tid & 31;
    const int wid  = tid >> 5;

    float v  = p[tid];
    float ss = v * v;
#pragma unroll
    for (int o = 16; o; o >>= 1) ss += __shfl_xor_sync(0xffffffffu, ss, o);

    __shared__ float red[4];
    if (lane == 0) red[wid] = ss;
    __syncthreads();
    float tot = red[0] + red[1] + red[2] + red[3];
    float r = rsqrtf(tot * (1.0f / HEAD_DIM) + 1e-5f);
    p[tid] = w[tid] * v * r;
}

// ---------------------------------------------------------------------------
// Row softmax over KVLEN columns, in place. blockIdx.x = row; 256 threads.
// ---------------------------------------------------------------------------
__global__ void softmax_rows(float* __restrict__ S)
{
    float* row = S + (size_t)blockIdx.x * KVLEN;
    const int tid  = threadIdx.x;
    const int lane = tid & 31;
    const int wid  = tid >> 5;
    __shared__ float red[8];

    float m = -1e30f;
    for (int i = tid; i < KVLEN; i += 256) m = fmaxf(m, row[i]);
#pragma unroll
    for (int o = 16; o; o >>= 1) m = fmaxf(m, __shfl_xor_sync(0xffffffffu, m, o));
    if (lane == 0) red[wid] = m;
    __syncthreads();
    m = red[0];
#pragma unroll
    for (int w2 = 1; w2 < 8; w2++) m = fmaxf(m, red[w2]);

    float sum = 0.f;
    for (int i = tid; i < KVLEN; i += 256) {
        float e = __expf(row[i] - m);
        row[i] = e;
        sum += e;
    }
#pragma unroll
    for (int o = 16; o; o >>= 1) sum += __shfl_xor_sync(0xffffffffu, sum, o);
    __syncthreads();
    if (lane == 0) red[wid] = sum;
    __syncthreads();
    sum = 0.f;
#pragma unroll
    for (int w2 = 0; w2 < 8; w2++) sum += red[w2];
    float inv = 1.0f / sum;
    for (int i = tid; i < KVLEN; i += 256) row[i] *= inv;
}

// ---------------------------------------------------------------------------
// Launch
// ---------------------------------------------------------------------------
extern "C" void kernel_launch(void* const* d_in, const int* in_sizes, int n_in,
                              void* d_out, int out_size)
{
    const float* hs = (const float*)d_in[0];   // [1, 1024, 4096]
    const float* kv = (const float*)d_in[1];   // [1, 4096, 4096]
    const float* wq = (const float*)d_in[2];   // [4096, 4096]
    const float* wk = (const float*)d_in[3];
    const float* wv = (const float*)d_in[4];
    const float* wo = (const float*)d_in[5];
    const float* qw = (const float*)d_in[6];   // [128]
    const float* kw = (const float*)d_in[7];   // [128]
    float* out = (float*)d_out;                // [1, 1024, 4096]

    float *q, *k, *v, *s, *attn;
    cudaGetSymbolAddress((void**)&q,    g_q);
    cudaGetSymbolAddress((void**)&k,    g_k);
    cudaGetSymbolAddress((void**)&v,    g_v);
    cudaGetSymbolAddress((void**)&s,    g_s);
    cudaGetSymbolAddress((void**)&attn, g_attn);

    const dim3 thr(256);
    const float inv_sqrt_d = 0.08838834764831845f;   // 1/sqrt(128)

    // Q = hs @ wq^T   [1024, 4096]
    gemm_nt<<<dim3(HIDDEN / BN, QLEN / BM, 1), thr>>>(
        hs, wq, q, HIDDEN, HIDDEN, HIDDEN, HIDDEN, 0, 0, 0, 1.0f);
    // K = kv @ wk^T   [4096, 4096]
    gemm_nt<<<dim3(HIDDEN / BN, KVLEN / BM, 1), thr>>>(
        kv, wk, k, HIDDEN, HIDDEN, HIDDEN, HIDDEN, 0, 0, 0, 1.0f);
    // V = kv @ wv^T   [4096, 4096]
    gemm_nt<<<dim3(HIDDEN / BN, KVLEN / BM, 1), thr>>>(
        kv, wv, v, HIDDEN, HIDDEN, HIDDEN, HIDDEN, 0, 0, 0, 1.0f);

    // per-head RMSNorm (each row of Q/K is 32 heads x 128 contiguous dims)
    rmsnorm_128<<<QLEN * NUM_HEADS, HEAD_DIM>>>(q, qw);
    rmsnorm_128<<<KVLEN * NUM_HEADS, HEAD_DIM>>>(k, kw);

    // scores[h] = (Q_h @ K_h^T) / sqrt(d)  -> [32][1024][4096]
    gemm_nt<<<dim3(KVLEN / BN, QLEN / BM, NUM_HEADS), thr>>>(
        q, k, s, HEAD_DIM, HIDDEN, HIDDEN, KVLEN,
        (long)HEAD_DIM, (long)HEAD_DIM, (long)QLEN * KVLEN, inv_sqrt_d);

    // softmax over keys
    softmax_rows<<<NUM_HEADS * QLEN, 256>>>(s);

    // attn[h] = probs[h] @ V_h   -> columns h*128..h*128+127 of [1024, 4096]
    gemm_nn<<<dim3(HEAD_DIM / BN == 0 ? 1 : HEAD_DIM / BN, QLEN / BM, NUM_HEADS), thr>>>(
        s, v, attn, KVLEN, KVLEN, HIDDEN, HIDDEN,
        (long)QLEN * KVLEN, (long)HEAD_DIM, (long)HEAD_DIM, 1.0f);

    // out = attn @ wo^T   [1024, 4096]
    gemm_nt<<<dim3(HIDDEN / BN, QLEN / BM, 1), thr>>>(
        attn, wo, out, HIDDEN, HIDDEN, HIDDEN, HIDDEN, 0, 0, 0, 1.0f);
}